// round 3
// baseline (speedup 1.0000x reference)
#include <cuda_runtime.h>

#define EPS_BN 1e-3f
#define MAXN 200000

// ---------------- scratch (__device__ globals; no allocation allowed) --------
__device__ __align__(16) float g_y1[MAXN * 64];    // stage-1 pre-BN output
__device__ __align__(16) float g_y2[MAXN * 64];    // stage-2 pre-BN output
__device__ __align__(16) float g_y3[MAXN * 256];   // stage-3 pre-BN output
__device__ __align__(16) float g_sum[3 * 256];
__device__ __align__(16) float g_sumsq[3 * 256];
__device__ __align__(16) float g_scale[3 * 256];
__device__ __align__(16) float g_shift[3 * 256];

// ---------------------------------------------------------------------------
__global__ void zero_stats_kernel() {
    int i = threadIdx.x;
    if (i < 768) { g_sum[i] = 0.f; g_sumsq[i] = 0.f; }
}

// y1 = x @ W1   [N,256]x[256,64], accumulate stage-0 column stats
__global__ __launch_bounds__(256) void gemm1_kernel(const float* __restrict__ x,
                                                    const float* __restrict__ W1,
                                                    int n) {
    __shared__ float Ash[128][32];
    __shared__ float Bsh[32][64];
    __shared__ float Rsum[16][64];
    __shared__ float Rsq[16][64];
    int tid = threadIdx.x;
    int cx = tid & 15;      // col group: cols [4cx, 4cx+4)
    int ty = tid >> 4;      // row group: rows [8ty, 8ty+8)
    int rowBase = blockIdx.x * 128;

    float acc[8][4];
#pragma unroll
    for (int i = 0; i < 8; i++)
#pragma unroll
        for (int j = 0; j < 4; j++) acc[i][j] = 0.f;

    for (int k0 = 0; k0 < 256; k0 += 32) {
        // A tile: 128x32 = 1024 float4, 4 per thread
#pragma unroll
        for (int i = 0; i < 4; i++) {
            int f = tid + 256 * i;
            int r = f >> 3, c4 = f & 7;
            int gr = rowBase + r;
            float4 v = make_float4(0.f, 0.f, 0.f, 0.f);
            if (gr < n) v = *(const float4*)&x[(size_t)gr * 256 + k0 + c4 * 4];
            *(float4*)&Ash[r][c4 * 4] = v;
        }
        // B tile: 32x64 = 512 float4, 2 per thread
#pragma unroll
        for (int i = 0; i < 2; i++) {
            int f = tid + 256 * i;
            int r = f >> 4, c4 = f & 15;
            *(float4*)&Bsh[r][c4 * 4] = *(const float4*)&W1[(size_t)(k0 + r) * 64 + c4 * 4];
        }
        __syncthreads();
#pragma unroll
        for (int kk = 0; kk < 32; kk++) {
            float4 b = *(float4*)&Bsh[kk][cx * 4];
#pragma unroll
            for (int i = 0; i < 8; i++) {
                float a = Ash[ty * 8 + i][kk];
                acc[i][0] = fmaf(a, b.x, acc[i][0]);
                acc[i][1] = fmaf(a, b.y, acc[i][1]);
                acc[i][2] = fmaf(a, b.z, acc[i][2]);
                acc[i][3] = fmaf(a, b.w, acc[i][3]);
            }
        }
        __syncthreads();
    }

    float cs[4] = {0.f, 0.f, 0.f, 0.f}, cq[4] = {0.f, 0.f, 0.f, 0.f};
#pragma unroll
    for (int i = 0; i < 8; i++) {
        int gr = rowBase + ty * 8 + i;
        if (gr < n) {
            *(float4*)&g_y1[(size_t)gr * 64 + cx * 4] =
                make_float4(acc[i][0], acc[i][1], acc[i][2], acc[i][3]);
#pragma unroll
            for (int j = 0; j < 4; j++) {
                cs[j] += acc[i][j];
                cq[j] += acc[i][j] * acc[i][j];
            }
        }
    }
#pragma unroll
    for (int j = 0; j < 4; j++) { Rsum[ty][cx * 4 + j] = cs[j]; Rsq[ty][cx * 4 + j] = cq[j]; }
    __syncthreads();
    if (tid < 64) {
        float s = 0.f, q = 0.f;
#pragma unroll
        for (int t = 0; t < 16; t++) { s += Rsum[t][tid]; q += Rsq[t][tid]; }
        atomicAdd(&g_sum[tid], s);
        atomicAdd(&g_sumsq[tid], q);
    }
}

__global__ void bn_finalize_kernel(const float* __restrict__ gamma,
                                   const float* __restrict__ beta,
                                   int C, int stage, float invN) {
    int c = threadIdx.x;
    if (c < C) {
        float mean = g_sum[stage * 256 + c] * invN;
        float var  = g_sumsq[stage * 256 + c] * invN - mean * mean;
        float s = gamma[c] * rsqrtf(var + EPS_BN);
        g_scale[stage * 256 + c] = s;
        g_shift[stage * 256 + c] = beta[c] - mean * s;
    }
}

// y2 = sum_k relu(bn1(y1))[neigh[:,k]] @ W2[k],  stage-1 stats. BN1+ReLU fused into gather.
__global__ __launch_bounds__(256) void gemm2_kernel(const int* __restrict__ neigh,
                                                    const float* __restrict__ W2,
                                                    int n) {
    __shared__ float Ash[128][64];  // 32 KB
    __shared__ float Bsh[64][64];   // 16 KB  (reused for stat reduction)
    int tid = threadIdx.x;
    int cx = tid & 15, ty = tid >> 4;
    int rowBase = blockIdx.x * 128;

    float4 s1 = *(const float4*)&g_scale[cx * 4];
    float4 t1 = *(const float4*)&g_shift[cx * 4];

    float acc[8][4];
#pragma unroll
    for (int i = 0; i < 8; i++)
#pragma unroll
        for (int j = 0; j < 4; j++) acc[i][j] = 0.f;

    for (int k = 0; k < 27; k++) {
        // W2[k]: 64x64 = 1024 float4, 4 per thread
#pragma unroll
        for (int i = 0; i < 4; i++) {
            int f = tid + 256 * i;
            int r = f >> 4, c4 = f & 15;
            *(float4*)&Bsh[r][c4 * 4] =
                *(const float4*)&W2[((size_t)k * 64 + r) * 64 + c4 * 4];
        }
        // gather 128 rows of h1 (BN1+ReLU applied on the fly)
#pragma unroll
        for (int i = 0; i < 8; i++) {
            int r = ty + 16 * i;
            int gr = rowBase + r;
            float4 v = make_float4(0.f, 0.f, 0.f, 0.f);
            if (gr < n) {
                int idx = __ldg(&neigh[(size_t)gr * 27 + k]);
                float4 y = *(const float4*)&g_y1[(size_t)idx * 64 + cx * 4];
                v.x = fmaxf(fmaf(y.x, s1.x, t1.x), 0.f);
                v.y = fmaxf(fmaf(y.y, s1.y, t1.y), 0.f);
                v.z = fmaxf(fmaf(y.z, s1.z, t1.z), 0.f);
                v.w = fmaxf(fmaf(y.w, s1.w, t1.w), 0.f);
            }
            *(float4*)&Ash[r][cx * 4] = v;
        }
        __syncthreads();
#pragma unroll 16
        for (int kk = 0; kk < 64; kk++) {
            float4 b = *(float4*)&Bsh[kk][cx * 4];
#pragma unroll
            for (int i = 0; i < 8; i++) {
                float a = Ash[ty * 8 + i][kk];
                acc[i][0] = fmaf(a, b.x, acc[i][0]);
                acc[i][1] = fmaf(a, b.y, acc[i][1]);
                acc[i][2] = fmaf(a, b.z, acc[i][2]);
                acc[i][3] = fmaf(a, b.w, acc[i][3]);
            }
        }
        __syncthreads();
    }

    float cs[4] = {0.f, 0.f, 0.f, 0.f}, cq[4] = {0.f, 0.f, 0.f, 0.f};
#pragma unroll
    for (int i = 0; i < 8; i++) {
        int gr = rowBase + ty * 8 + i;
        if (gr < n) {
            *(float4*)&g_y2[(size_t)gr * 64 + cx * 4] =
                make_float4(acc[i][0], acc[i][1], acc[i][2], acc[i][3]);
#pragma unroll
            for (int j = 0; j < 4; j++) {
                cs[j] += acc[i][j];
                cq[j] += acc[i][j] * acc[i][j];
            }
        }
    }
    float* red = &Bsh[0][0];  // safe: all threads past last __syncthreads of k-loop
#pragma unroll
    for (int j = 0; j < 4; j++) {
        red[ty * 64 + cx * 4 + j] = cs[j];
        red[1024 + ty * 64 + cx * 4 + j] = cq[j];
    }
    __syncthreads();
    if (tid < 64) {
        float s = 0.f, q = 0.f;
#pragma unroll
        for (int t = 0; t < 16; t++) { s += red[t * 64 + tid]; q += red[1024 + t * 64 + tid]; }
        atomicAdd(&g_sum[256 + tid], s);
        atomicAdd(&g_sumsq[256 + tid], q);
    }
}

// y3 = relu(bn2(y2)) @ W3  [N,64]x[64,256], stage-2 stats. BN2+ReLU fused into A load.
__global__ __launch_bounds__(256) void gemm3_kernel(const float* __restrict__ W3, int n) {
    __shared__ float Ash[128][64];
    __shared__ float Bsh[64][64];   // reused for stat reduction
    int tid = threadIdx.x;
    int cx = tid & 15, ty = tid >> 4;
    int rowBase = blockIdx.x * 128;
    int colBase = blockIdx.y * 64;

    float4 s2 = *(const float4*)&g_scale[256 + cx * 4];
    float4 t2 = *(const float4*)&g_shift[256 + cx * 4];

#pragma unroll
    for (int i = 0; i < 8; i++) {
        int r = ty + 16 * i;
        int gr = rowBase + r;
        float4 v = make_float4(0.f, 0.f, 0.f, 0.f);
        if (gr < n) {
            float4 y = *(const float4*)&g_y2[(size_t)gr * 64 + cx * 4];
            v.x = fmaxf(fmaf(y.x, s2.x, t2.x), 0.f);
            v.y = fmaxf(fmaf(y.y, s2.y, t2.y), 0.f);
            v.z = fmaxf(fmaf(y.z, s2.z, t2.z), 0.f);
            v.w = fmaxf(fmaf(y.w, s2.w, t2.w), 0.f);
        }
        *(float4*)&Ash[r][cx * 4] = v;
    }
#pragma unroll
    for (int i = 0; i < 4; i++) {
        int f = tid + 256 * i;
        int r = f >> 4, c4 = f & 15;
        *(float4*)&Bsh[r][c4 * 4] = *(const float4*)&W3[(size_t)r * 256 + colBase + c4 * 4];
    }
    __syncthreads();

    float acc[8][4];
#pragma unroll
    for (int i = 0; i < 8; i++)
#pragma unroll
        for (int j = 0; j < 4; j++) acc[i][j] = 0.f;

#pragma unroll 16
    for (int kk = 0; kk < 64; kk++) {
        float4 b = *(float4*)&Bsh[kk][cx * 4];
#pragma unroll
        for (int i = 0; i < 8; i++) {
            float a = Ash[ty * 8 + i][kk];
            acc[i][0] = fmaf(a, b.x, acc[i][0]);
            acc[i][1] = fmaf(a, b.y, acc[i][1]);
            acc[i][2] = fmaf(a, b.z, acc[i][2]);
            acc[i][3] = fmaf(a, b.w, acc[i][3]);
        }
    }
    __syncthreads();

    float cs[4] = {0.f, 0.f, 0.f, 0.f}, cq[4] = {0.f, 0.f, 0.f, 0.f};
#pragma unroll
    for (int i = 0; i < 8; i++) {
        int gr = rowBase + ty * 8 + i;
        if (gr < n) {
            *(float4*)&g_y3[(size_t)gr * 256 + colBase + cx * 4] =
                make_float4(acc[i][0], acc[i][1], acc[i][2], acc[i][3]);
#pragma unroll
            for (int j = 0; j < 4; j++) {
                cs[j] += acc[i][j];
                cq[j] += acc[i][j] * acc[i][j];
            }
        }
    }
    float* red = &Bsh[0][0];
#pragma unroll
    for (int j = 0; j < 4; j++) {
        red[ty * 64 + cx * 4 + j] = cs[j];
        red[1024 + ty * 64 + cx * 4 + j] = cq[j];
    }
    __syncthreads();
    if (tid < 64) {
        float s = 0.f, q = 0.f;
#pragma unroll
        for (int t = 0; t < 16; t++) { s += red[t * 64 + tid]; q += red[1024 + t * 64 + tid]; }
        atomicAdd(&g_sum[512 + colBase + tid], s);
        atomicAdd(&g_sumsq[512 + colBase + tid], q);
    }
}

// out = relu(bn3(y3) + x)
__global__ __launch_bounds__(256) void final_kernel(const float* __restrict__ x,
                                                    float* __restrict__ out, int n) {
    long i = (long)blockIdx.x * blockDim.x + threadIdx.x;   // float4 index
    long total4 = (long)n * 64;
    if (i < total4) {
        int c4 = (int)(i & 63);
        float4 y = *(const float4*)&g_y3[i * 4];
        float4 xi = *(const float4*)&x[i * 4];
        float4 s = *(const float4*)&g_scale[512 + c4 * 4];
        float4 t = *(const float4*)&g_shift[512 + c4 * 4];
        float4 o;
        o.x = fmaxf(fmaf(y.x, s.x, t.x) + xi.x, 0.f);
        o.y = fmaxf(fmaf(y.y, s.y, t.y) + xi.y, 0.f);
        o.z = fmaxf(fmaf(y.z, s.z, t.z) + xi.z, 0.f);
        o.w = fmaxf(fmaf(y.w, s.w, t.w) + xi.w, 0.f);
        *(float4*)&out[i * 4] = o;
    }
}

// ---------------------------------------------------------------------------
extern "C" void kernel_launch(void* const* d_in, const int* in_sizes, int n_in,
                              void* d_out, int out_size) {
    const float* x     = (const float*)d_in[0];
    const int*   neigh = (const int*)d_in[1];
    // d_in[2] = depth (unused)
    const float* W1 = (const float*)d_in[3];
    const float* g1 = (const float*)d_in[4];
    const float* b1 = (const float*)d_in[5];
    const float* W2 = (const float*)d_in[6];
    const float* g2 = (const float*)d_in[7];
    const float* b2 = (const float*)d_in[8];
    const float* W3 = (const float*)d_in[9];
    const float* g3 = (const float*)d_in[10];
    const float* b3 = (const float*)d_in[11];
    float* out = (float*)d_out;

    int n = in_sizes[0] / 256;
    int NB = (n + 127) / 128;
    float invN = 1.0f / (float)n;

    zero_stats_kernel<<<1, 768>>>();
    gemm1_kernel<<<NB, 256>>>(x, W1, n);
    bn_finalize_kernel<<<1, 256>>>(g1, b1, 64, 0, invN);
    gemm2_kernel<<<NB, 256>>>(neigh, W2, n);
    bn_finalize_kernel<<<1, 256>>>(g2, b2, 64, 1, invN);
    gemm3_kernel<<<dim3(NB, 4), 256>>>(W3, n);
    bn_finalize_kernel<<<1, 256>>>(g3, b3, 256, 2, invN);
    long total4 = (long)n * 64;
    final_kernel<<<(int)((total4 + 255) / 256), 256>>>(x, out, n);
}

// round 13
// speedup vs baseline: 1.6694x; 1.6694x over previous
#include <cuda_runtime.h>
#include <cstdint>

#define EPS_BN 1e-3f
#define MAXN 200000

// ---------------- scratch (__device__ globals; no allocation allowed) --------
__device__ __align__(16) float    g_y1[MAXN * 64];     // stage-1 pre-BN output
__device__ __align__(16) uint32_t g_h1t[MAXN * 64];    // tf32(relu(bn1(y1)))
__device__ __align__(16) float    g_y2[MAXN * 64];     // stage-2 pre-BN output
__device__ __align__(16) uint32_t g_h2t[MAXN * 64];    // tf32(relu(bn2(y2)))
__device__ __align__(16) float    g_y3[MAXN * 256];    // stage-3 pre-BN output
__device__ __align__(16) uint32_t g_W1t[256 * 64];     // tf32 W1 [k][n]
__device__ __align__(16) uint32_t g_W2t[27 * 64 * 64]; // tf32 W2 [tap][k][n] (native)
__device__ __align__(16) uint32_t g_W3t[64 * 256];     // tf32 W3 [k][n]
__device__ __align__(16) float g_sum[3 * 256];
__device__ __align__(16) float g_sumsq[3 * 256];
__device__ __align__(16) float g_scale[3 * 256];
__device__ __align__(16) float g_shift[3 * 256];

// ---------------------------- helpers ---------------------------------------
__device__ __forceinline__ uint32_t f2tf32(float v) {
    uint32_t u;
    asm("cvt.rna.tf32.f32 %0, %1;" : "=r"(u) : "f"(v));
    return u;
}

// D += A(16x8 tf32, row) * B(8x8 tf32, col)
__device__ __forceinline__ void mma16n8k8(float* d, const uint32_t* a, const uint32_t* b) {
    asm volatile(
        "mma.sync.aligned.m16n8k8.row.col.f32.tf32.tf32.f32 "
        "{%0,%1,%2,%3}, {%4,%5,%6,%7}, {%8,%9}, {%0,%1,%2,%3};"
        : "+f"(d[0]), "+f"(d[1]), "+f"(d[2]), "+f"(d[3])
        : "r"(a[0]), "r"(a[1]), "r"(a[2]), "r"(a[3]), "r"(b[0]), "r"(b[1]));
}

// Smem layout (dynamic): As = 128 rows x 68 words (A, M x K, row-major, tf32 bits)
//                        Bs =  64 rows x 72 words (B, K x N, n in row, tf32 bits)
#define A_STRIDE 68
#define B_STRIDE 72
#define AS_WORDS (128 * A_STRIDE)                 // 8704
#define BS_WORDS (64 * B_STRIDE)                  // 4608
#define TC_SMEM  ((AS_WORDS + BS_WORDS) * 4)      // 53248 bytes

// Warp-tile MMA step over one 128x64(A) x 64x64(B) pair of smem tiles.
// acc[2][4][4] per thread. wm in 0..3 (rows wm*32), wn in 0..1 (cols wn*32).
__device__ __forceinline__ void tile_mma(const uint32_t* As, const uint32_t* Bs,
                                         int wm, int wn, int g, int tg,
                                         float acc[2][4][4]) {
#pragma unroll
    for (int kt = 0; kt < 8; kt++) {
        int c0 = kt * 8 + tg;
        uint32_t a[2][4];
#pragma unroll
        for (int mt = 0; mt < 2; mt++) {
            int r = wm * 32 + mt * 16 + g;
            a[mt][0] = As[r * A_STRIDE + c0];
            a[mt][1] = As[(r + 8) * A_STRIDE + c0];
            a[mt][2] = As[r * A_STRIDE + c0 + 4];
            a[mt][3] = As[(r + 8) * A_STRIDE + c0 + 4];
        }
        uint32_t b[4][2];
#pragma unroll
        for (int nt = 0; nt < 4; nt++) {
            int nn = wn * 32 + nt * 8 + g;
            b[nt][0] = Bs[(kt * 8 + tg) * B_STRIDE + nn];
            b[nt][1] = Bs[(kt * 8 + tg + 4) * B_STRIDE + nn];
        }
#pragma unroll
        for (int mt = 0; mt < 2; mt++)
#pragma unroll
            for (int nt = 0; nt < 4; nt++) mma16n8k8(acc[mt][nt], a[mt], b[nt]);
    }
}

// Epilogue: write acc into red (smem, 128x68) + out rows (64-wide slab at outStride),
// then column sum/sumsq reduce -> atomicAdd into g_sum/g_sumsq at statBase.
__device__ __forceinline__ void tile_epilogue(float* red, float* outBase, size_t outStride,
                                              int rowBase, int n, int wm, int wn,
                                              int g, int tg, int tid, int statBase,
                                              float acc[2][4][4]) {
#pragma unroll
    for (int mt = 0; mt < 2; mt++) {
        int r = wm * 32 + mt * 16 + g;
#pragma unroll
        for (int nt = 0; nt < 4; nt++) {
            int c = wn * 32 + nt * 8 + tg * 2;
            red[r * A_STRIDE + c]           = acc[mt][nt][0];
            red[r * A_STRIDE + c + 1]       = acc[mt][nt][1];
            red[(r + 8) * A_STRIDE + c]     = acc[mt][nt][2];
            red[(r + 8) * A_STRIDE + c + 1] = acc[mt][nt][3];
            int gr = rowBase + r;
            if (gr < n)
                *(float2*)&outBase[(size_t)gr * outStride + c] =
                    make_float2(acc[mt][nt][0], acc[mt][nt][1]);
            if (gr + 8 < n)
                *(float2*)&outBase[(size_t)(gr + 8) * outStride + c] =
                    make_float2(acc[mt][nt][2], acc[mt][nt][3]);
        }
    }
    __syncthreads();
    if (tid < 64) {
        float s = 0.f, q = 0.f;
#pragma unroll 8
        for (int r = 0; r < 128; r++) {
            float v = red[r * A_STRIDE + tid];
            s += v; q += v * v;
        }
        atomicAdd(&g_sum[statBase + tid], s);
        atomicAdd(&g_sumsq[statBase + tid], q);
    }
}

// ---------------------------------------------------------------------------
__global__ void zero_stats_kernel() {
    int i = threadIdx.x;
    if (i < 768) { g_sum[i] = 0.f; g_sumsq[i] = 0.f; }
}

// Convert W1, W2, W3 to tf32 bits (native layouts, no transpose needed).
__global__ void prep_weights_kernel(const float* __restrict__ W1,
                                    const float* __restrict__ W2,
                                    const float* __restrict__ W3) {
    int i = blockIdx.x * 256 + threadIdx.x;
    if (i < 16384) g_W1t[i] = f2tf32(W1[i]);
    if (i < 110592) g_W2t[i] = f2tf32(W2[i]);
    if (i >= 110592 && i < 110592 + 16384) g_W3t[i - 110592] = f2tf32(W3[i - 110592]);
}

__global__ void bn_finalize_kernel(const float* __restrict__ gamma,
                                   const float* __restrict__ beta,
                                   int C, int stage, float invN) {
    int c = threadIdx.x;
    if (c < C) {
        float mean = g_sum[stage * 256 + c] * invN;
        float var  = g_sumsq[stage * 256 + c] * invN - mean * mean;
        float s = gamma[c] * rsqrtf(var + EPS_BN);
        g_scale[stage * 256 + c] = s;
        g_shift[stage * 256 + c] = beta[c] - mean * s;
    }
}

// h{1,2}t = tf32(relu(bn(y)))  — one conversion per node, hoisted out of gemm2/3.
// NOTE: y/ht selected INSIDE the kernel from `stage` — passing __device__ global
// symbols as host-side kernel args gives the host shadow address (that was the
// round-10 correctness bug).
__global__ __launch_bounds__(256) void prep_h_kernel(int stage, int n) {
    const float* __restrict__ y = (stage == 0) ? g_y1 : g_y2;
    uint32_t* __restrict__ ht   = (stage == 0) ? g_h1t : g_h2t;
    long i = (long)blockIdx.x * 256 + threadIdx.x;   // float4 index
    long total4 = (long)n * 16;
    if (i < total4) {
        int c4 = (int)(i & 15) * 4;
        float4 v = *(const float4*)&y[i * 4];
        float4 s = *(const float4*)&g_scale[stage * 256 + c4];
        float4 t = *(const float4*)&g_shift[stage * 256 + c4];
        uint4 o;
        o.x = f2tf32(fmaxf(fmaf(v.x, s.x, t.x), 0.f));
        o.y = f2tf32(fmaxf(fmaf(v.y, s.y, t.y), 0.f));
        o.z = f2tf32(fmaxf(fmaf(v.z, s.z, t.z), 0.f));
        o.w = f2tf32(fmaxf(fmaf(v.w, s.w, t.w), 0.f));
        *(uint4*)&ht[i * 4] = o;
    }
}

// ---------------- stage 1: y1 = x @ W1  (tf32 mma, K=256 in 4 chunks) -------
__global__ __launch_bounds__(256) void gemm1_tc_kernel(const float* __restrict__ x, int n) {
    extern __shared__ uint32_t smem[];
    uint32_t* As = smem;
    uint32_t* Bs = smem + AS_WORDS;
    int tid = threadIdx.x, lid = tid & 31;
    int g = lid >> 2, tg = lid & 3;
    int wid = tid >> 5, wm = wid & 3, wn = wid >> 2;
    int rowBase = blockIdx.x * 128;

    float acc[2][4][4];
#pragma unroll
    for (int mt = 0; mt < 2; mt++)
#pragma unroll
        for (int nt = 0; nt < 4; nt++)
#pragma unroll
            for (int e = 0; e < 4; e++) acc[mt][nt][e] = 0.f;

    for (int k0 = 0; k0 < 256; k0 += 64) {
        // A fill: x rows, cvt to tf32
#pragma unroll
        for (int i = 0; i < 8; i++) {
            int fid = tid + 256 * i;
            int r = fid >> 4, j = fid & 15;
            int gr = rowBase + r;
            uint4 v = make_uint4(0u, 0u, 0u, 0u);
            if (gr < n) {
                float4 xv = *(const float4*)&x[(size_t)gr * 256 + k0 + j * 4];
                v.x = f2tf32(xv.x); v.y = f2tf32(xv.y);
                v.z = f2tf32(xv.z); v.w = f2tf32(xv.w);
            }
            *(uint4*)&As[r * A_STRIDE + j * 4] = v;
        }
        // B fill: W1t rows k0..k0+63
#pragma unroll
        for (int i = 0; i < 4; i++) {
            int fid = tid + 256 * i;
            int kr = fid >> 4, j = fid & 15;
            *(uint4*)&Bs[kr * B_STRIDE + j * 4] =
                *(const uint4*)&g_W1t[(size_t)(k0 + kr) * 64 + j * 4];
        }
        __syncthreads();
        tile_mma(As, Bs, wm, wn, g, tg, acc);
        __syncthreads();
    }
    tile_epilogue((float*)As, g_y1, 64, rowBase, n, wm, wn, g, tg, tid, 0, acc);
}

// ------ stage 2: y2 = sum_k h1t[neigh[:,k]] @ W2[k]  (tf32 mma, 27 taps) ----
__global__ __launch_bounds__(256) void gemm2_tc_kernel(const int* __restrict__ neigh, int n) {
    extern __shared__ uint32_t smem[];
    uint32_t* As = smem;
    uint32_t* Bs = smem + AS_WORDS;
    int tid = threadIdx.x, lid = tid & 31;
    int g = lid >> 2, tg = lid & 3;
    int wid = tid >> 5, wm = wid & 3, wn = wid >> 2;
    int rowBase = blockIdx.x * 128;

    float acc[2][4][4];
#pragma unroll
    for (int mt = 0; mt < 2; mt++)
#pragma unroll
        for (int nt = 0; nt < 4; nt++)
#pragma unroll
            for (int e = 0; e < 4; e++) acc[mt][nt][e] = 0.f;

    for (int k = 0; k < 27; k++) {
        // A fill: pure gather copy of pre-converted h1t (16 lanes per row, coalesced)
#pragma unroll
        for (int i = 0; i < 8; i++) {
            int fid = tid + 256 * i;
            int r = fid >> 4, j = fid & 15;
            int gr = rowBase + r;
            uint4 v = make_uint4(0u, 0u, 0u, 0u);
            if (gr < n) {
                int idx = __ldg(&neigh[(size_t)gr * 27 + k]);
                v = *(const uint4*)&g_h1t[(size_t)idx * 64 + j * 4];
            }
            *(uint4*)&As[r * A_STRIDE + j * 4] = v;
        }
        // B fill: W2t[k] (native [k][n] layout)
#pragma unroll
        for (int i = 0; i < 4; i++) {
            int fid = tid + 256 * i;
            int kr = fid >> 4, j = fid & 15;
            *(uint4*)&Bs[kr * B_STRIDE + j * 4] =
                *(const uint4*)&g_W2t[((size_t)k * 64 + kr) * 64 + j * 4];
        }
        __syncthreads();
        tile_mma(As, Bs, wm, wn, g, tg, acc);
        __syncthreads();
    }
    tile_epilogue((float*)As, g_y2, 64, rowBase, n, wm, wn, g, tg, tid, 256, acc);
}

// ---------------- stage 3: y3 = h2t @ W3  (tf32 mma, grid.y = col slab) -----
__global__ __launch_bounds__(256) void gemm3_tc_kernel(int n) {
    extern __shared__ uint32_t smem[];
    uint32_t* As = smem;
    uint32_t* Bs = smem + AS_WORDS;
    int tid = threadIdx.x, lid = tid & 31;
    int g = lid >> 2, tg = lid & 3;
    int wid = tid >> 5, wm = wid & 3, wn = wid >> 2;
    int rowBase = blockIdx.x * 128;
    int colBase = blockIdx.y * 64;

    float acc[2][4][4];
#pragma unroll
    for (int mt = 0; mt < 2; mt++)
#pragma unroll
        for (int nt = 0; nt < 4; nt++)
#pragma unroll
            for (int e = 0; e < 4; e++) acc[mt][nt][e] = 0.f;

    // A fill: h2t rows (single K=64 chunk)
#pragma unroll
    for (int i = 0; i < 8; i++) {
        int fid = tid + 256 * i;
        int r = fid >> 4, j = fid & 15;
        int gr = rowBase + r;
        uint4 v = make_uint4(0u, 0u, 0u, 0u);
        if (gr < n) v = *(const uint4*)&g_h2t[(size_t)gr * 64 + j * 4];
        *(uint4*)&As[r * A_STRIDE + j * 4] = v;
    }
    // B fill: W3t[k][colBase + 0..63]
#pragma unroll
    for (int i = 0; i < 4; i++) {
        int fid = tid + 256 * i;
        int kr = fid >> 4, j = fid & 15;
        *(uint4*)&Bs[kr * B_STRIDE + j * 4] =
            *(const uint4*)&g_W3t[(size_t)kr * 256 + colBase + j * 4];
    }
    __syncthreads();
    tile_mma(As, Bs, wm, wn, g, tg, acc);
    __syncthreads();
    tile_epilogue((float*)As, g_y3 + colBase, 256, rowBase, n, wm, wn, g, tg, tid,
                  512 + colBase, acc);
}

// out = relu(bn3(y3) + x)
__global__ __launch_bounds__(256) void final_kernel(const float* __restrict__ x,
                                                    float* __restrict__ out, int n) {
    long i = (long)blockIdx.x * blockDim.x + threadIdx.x;
    long total4 = (long)n * 64;
    if (i < total4) {
        int c4 = (int)(i & 63);
        float4 y = *(const float4*)&g_y3[i * 4];
        float4 xi = *(const float4*)&x[i * 4];
        float4 s = *(const float4*)&g_scale[512 + c4 * 4];
        float4 t = *(const float4*)&g_shift[512 + c4 * 4];
        float4 o;
        o.x = fmaxf(fmaf(y.x, s.x, t.x) + xi.x, 0.f);
        o.y = fmaxf(fmaf(y.y, s.y, t.y) + xi.y, 0.f);
        o.z = fmaxf(fmaf(y.z, s.z, t.z) + xi.z, 0.f);
        o.w = fmaxf(fmaf(y.w, s.w, t.w) + xi.w, 0.f);
        *(float4*)&out[i * 4] = o;
    }
}

// ---------------------------------------------------------------------------
extern "C" void kernel_launch(void* const* d_in, const int* in_sizes, int n_in,
                              void* d_out, int out_size) {
    const float* x     = (const float*)d_in[0];
    const int*   neigh = (const int*)d_in[1];
    const float* W1 = (const float*)d_in[3];
    const float* g1 = (const float*)d_in[4];
    const float* b1 = (const float*)d_in[5];
    const float* W2 = (const float*)d_in[6];
    const float* g2 = (const float*)d_in[7];
    const float* b2 = (const float*)d_in[8];
    const float* W3 = (const float*)d_in[9];
    const float* g3 = (const float*)d_in[10];
    const float* b3 = (const float*)d_in[11];
    float* out = (float*)d_out;

    int n = in_sizes[0] / 256;
    int NB = (n + 127) / 128;
    float invN = 1.0f / (float)n;

    static bool attr_done = false;
    if (!attr_done) {
        cudaFuncSetAttribute(gemm1_tc_kernel, cudaFuncAttributeMaxDynamicSharedMemorySize, TC_SMEM);
        cudaFuncSetAttribute(gemm2_tc_kernel, cudaFuncAttributeMaxDynamicSharedMemorySize, TC_SMEM);
        cudaFuncSetAttribute(gemm3_tc_kernel, cudaFuncAttributeMaxDynamicSharedMemorySize, TC_SMEM);
        attr_done = true;
    }

    zero_stats_kernel<<<1, 768>>>();
    prep_weights_kernel<<<(110592 + 16384 + 255) / 256, 256>>>(W1, W2, W3);
    gemm1_tc_kernel<<<NB, 256, TC_SMEM>>>(x, n);
    bn_finalize_kernel<<<1, 256>>>(g1, b1, 64, 0, invN);
    prep_h_kernel<<<(int)(((long)n * 16 + 255) / 256), 256>>>(0, n);
    gemm2_tc_kernel<<<NB, 256, TC_SMEM>>>(neigh, n);
    bn_finalize_kernel<<<1, 256>>>(g2, b2, 64, 1, invN);
    prep_h_kernel<<<(int)(((long)n * 16 + 255) / 256), 256>>>(1, n);
    gemm3_tc_kernel<<<dim3(NB, 4), 256, TC_SMEM>>>(n);
    bn_finalize_kernel<<<1, 256>>>(g3, b3, 256, 2, invN);
    long total4 = (long)n * 64;
    final_kernel<<<(int)((total4 + 255) / 256), 256>>>(x, out, n);
}

// round 15
// speedup vs baseline: 2.2314x; 1.3367x over previous
#include <cuda_runtime.h>
#include <cstdint>

#define EPS_BN 1e-3f
#define MAXN 200000

// ---------------- scratch (__device__ globals; no allocation allowed) --------
__device__ __align__(16) float    g_y1[MAXN * 64];     // stage-1 pre-BN output
__device__ __align__(16) uint32_t g_h1t[MAXN * 64];    // tf32(relu(bn1(y1)))
__device__ __align__(16) float    g_y2[MAXN * 64];     // stage-2 pre-BN output
__device__ __align__(16) uint32_t g_h2t[MAXN * 64];    // tf32(relu(bn2(y2)))
__device__ __align__(16) float    g_y3[MAXN * 256];    // stage-3 pre-BN output
__device__ __align__(16) uint32_t g_W1t[256 * 64];     // tf32 W1 [k][n]
__device__ __align__(16) uint32_t g_W2t[27 * 64 * 64]; // tf32 W2 [tap][k][n] (native)
__device__ __align__(16) uint32_t g_W3t[64 * 256];     // tf32 W3 [k][n]
__device__ __align__(16) float g_sum[3 * 256];
__device__ __align__(16) float g_sumsq[3 * 256];

// ---------------------------- helpers ---------------------------------------
__device__ __forceinline__ uint32_t f2tf32(float v) {
    uint32_t u;
    asm("cvt.rna.tf32.f32 %0, %1;" : "=r"(u) : "f"(v));
    return u;
}

// D += A(16x8 tf32, row) * B(8x8 tf32, col)
__device__ __forceinline__ void mma16n8k8(float* d, const uint32_t* a, const uint32_t* b) {
    asm volatile(
        "mma.sync.aligned.m16n8k8.row.col.f32.tf32.tf32.f32 "
        "{%0,%1,%2,%3}, {%4,%5,%6,%7}, {%8,%9}, {%0,%1,%2,%3};"
        : "+f"(d[0]), "+f"(d[1]), "+f"(d[2]), "+f"(d[3])
        : "r"(a[0]), "r"(a[1]), "r"(a[2]), "r"(a[3]), "r"(b[0]), "r"(b[1]));
}

// Smem tile: As = 128 rows x 68 words (M x K, row-major, tf32 bits)
//            Bs =  64 rows x 72 words (K x N, n in row, tf32 bits)
#define A_STRIDE 68
#define B_STRIDE 72
#define AS_WORDS (128 * A_STRIDE)                 // 8704
#define BS_WORDS (64 * B_STRIDE)                  // 4608
#define STAGE_WORDS (AS_WORDS + BS_WORDS)         // 13312
#define TC_SMEM  (STAGE_WORDS * 4)                // 53248 (single-stage kernels)
#define TC_SMEM2 (STAGE_WORDS * 2 * 4)            // 106496 (gemm2 double-buffered)

// Warp-tile MMA over one 128x64(A) x 64x64(B) smem tile pair.
__device__ __forceinline__ void tile_mma(const uint32_t* As, const uint32_t* Bs,
                                         int wm, int wn, int g, int tg,
                                         float acc[2][4][4]) {
#pragma unroll
    for (int kt = 0; kt < 8; kt++) {
        int c0 = kt * 8 + tg;
        uint32_t a[2][4];
#pragma unroll
        for (int mt = 0; mt < 2; mt++) {
            int r = wm * 32 + mt * 16 + g;
            a[mt][0] = As[r * A_STRIDE + c0];
            a[mt][1] = As[(r + 8) * A_STRIDE + c0];
            a[mt][2] = As[r * A_STRIDE + c0 + 4];
            a[mt][3] = As[(r + 8) * A_STRIDE + c0 + 4];
        }
        uint32_t b[4][2];
#pragma unroll
        for (int nt = 0; nt < 4; nt++) {
            int nn = wn * 32 + nt * 8 + g;
            b[nt][0] = Bs[(kt * 8 + tg) * B_STRIDE + nn];
            b[nt][1] = Bs[(kt * 8 + tg + 4) * B_STRIDE + nn];
        }
#pragma unroll
        for (int mt = 0; mt < 2; mt++)
#pragma unroll
            for (int nt = 0; nt < 4; nt++) mma16n8k8(acc[mt][nt], a[mt], b[nt]);
    }
}

// Epilogue: acc -> red smem + gmem slab, then column sum/sumsq -> atomicAdd.
__device__ __forceinline__ void tile_epilogue(float* red, float* outBase, size_t outStride,
                                              int rowBase, int n, int wm, int wn,
                                              int g, int tg, int tid, int statBase,
                                              float acc[2][4][4]) {
#pragma unroll
    for (int mt = 0; mt < 2; mt++) {
        int r = wm * 32 + mt * 16 + g;
#pragma unroll
        for (int nt = 0; nt < 4; nt++) {
            int c = wn * 32 + nt * 8 + tg * 2;
            red[r * A_STRIDE + c]           = acc[mt][nt][0];
            red[r * A_STRIDE + c + 1]       = acc[mt][nt][1];
            red[(r + 8) * A_STRIDE + c]     = acc[mt][nt][2];
            red[(r + 8) * A_STRIDE + c + 1] = acc[mt][nt][3];
            int gr = rowBase + r;
            if (gr < n)
                *(float2*)&outBase[(size_t)gr * outStride + c] =
                    make_float2(acc[mt][nt][0], acc[mt][nt][1]);
            if (gr + 8 < n)
                *(float2*)&outBase[(size_t)(gr + 8) * outStride + c] =
                    make_float2(acc[mt][nt][2], acc[mt][nt][3]);
        }
    }
    __syncthreads();
    if (tid < 64) {
        float s = 0.f, q = 0.f;
#pragma unroll 8
        for (int r = 0; r < 128; r++) {
            float v = red[r * A_STRIDE + tid];
            s += v; q += v * v;
        }
        atomicAdd(&g_sum[statBase + tid], s);
        atomicAdd(&g_sumsq[statBase + tid], q);
    }
}

// ---------------------------------------------------------------------------
// Fused: zero stats + convert W1/W2/W3 to tf32 bits.
__global__ void prep_kernel(const float* __restrict__ W1,
                            const float* __restrict__ W2,
                            const float* __restrict__ W3) {
    int i = blockIdx.x * 256 + threadIdx.x;
    if (i < 768) { g_sum[i] = 0.f; g_sumsq[i] = 0.f; }
    if (i < 16384) g_W1t[i] = f2tf32(W1[i]);
    if (i < 110592) g_W2t[i] = f2tf32(W2[i]);
    if (i >= 110592 && i < 110592 + 16384) g_W3t[i - 110592] = f2tf32(W3[i - 110592]);
}

// h{1,2}t = tf32(relu(bn(y))) — BN scale/shift recomputed per block (cheap),
// eliminating the separate bn_finalize launch.
__global__ __launch_bounds__(256) void prep_h_kernel(const float* __restrict__ gamma,
                                                     const float* __restrict__ beta,
                                                     int stage, int n, float invN) {
    __shared__ float s_sc[64], s_sh[64];
    const float* __restrict__ y = (stage == 0) ? g_y1 : g_y2;
    uint32_t* __restrict__ ht   = (stage == 0) ? g_h1t : g_h2t;
    int tid = threadIdx.x;
    if (tid < 64) {
        float mean = g_sum[stage * 256 + tid] * invN;
        float var  = g_sumsq[stage * 256 + tid] * invN - mean * mean;
        float s = gamma[tid] * rsqrtf(var + EPS_BN);
        s_sc[tid] = s;
        s_sh[tid] = beta[tid] - mean * s;
    }
    __syncthreads();
    long i = (long)blockIdx.x * 256 + tid;   // float4 index
    long total4 = (long)n * 16;
    if (i < total4) {
        int c4 = (int)(i & 15) * 4;
        float4 v = *(const float4*)&y[i * 4];
        float4 s = *(const float4*)&s_sc[c4];
        float4 t = *(const float4*)&s_sh[c4];
        uint4 o;
        o.x = f2tf32(fmaxf(fmaf(v.x, s.x, t.x), 0.f));
        o.y = f2tf32(fmaxf(fmaf(v.y, s.y, t.y), 0.f));
        o.z = f2tf32(fmaxf(fmaf(v.z, s.z, t.z), 0.f));
        o.w = f2tf32(fmaxf(fmaf(v.w, s.w, t.w), 0.f));
        *(uint4*)&ht[i * 4] = o;
    }
}

// ---------------- stage 1: y1 = x @ W1  (tf32 mma, K=256 in 4 chunks) -------
__global__ __launch_bounds__(256) void gemm1_tc_kernel(const float* __restrict__ x, int n) {
    extern __shared__ uint32_t smem[];
    uint32_t* As = smem;
    uint32_t* Bs = smem + AS_WORDS;
    int tid = threadIdx.x, lid = tid & 31;
    int g = lid >> 2, tg = lid & 3;
    int wid = tid >> 5, wm = wid & 3, wn = wid >> 2;
    int rowBase = blockIdx.x * 128;

    float acc[2][4][4];
#pragma unroll
    for (int mt = 0; mt < 2; mt++)
#pragma unroll
        for (int nt = 0; nt < 4; nt++)
#pragma unroll
            for (int e = 0; e < 4; e++) acc[mt][nt][e] = 0.f;

    for (int k0 = 0; k0 < 256; k0 += 64) {
#pragma unroll
        for (int i = 0; i < 8; i++) {
            int fid = tid + 256 * i;
            int r = fid >> 4, j = fid & 15;
            int gr = rowBase + r;
            uint4 v = make_uint4(0u, 0u, 0u, 0u);
            if (gr < n) {
                float4 xv = *(const float4*)&x[(size_t)gr * 256 + k0 + j * 4];
                v.x = f2tf32(xv.x); v.y = f2tf32(xv.y);
                v.z = f2tf32(xv.z); v.w = f2tf32(xv.w);
            }
            *(uint4*)&As[r * A_STRIDE + j * 4] = v;
        }
#pragma unroll
        for (int i = 0; i < 4; i++) {
            int fid = tid + 256 * i;
            int kr = fid >> 4, j = fid & 15;
            *(uint4*)&Bs[kr * B_STRIDE + j * 4] =
                *(const uint4*)&g_W1t[(size_t)(k0 + kr) * 64 + j * 4];
        }
        __syncthreads();
        tile_mma(As, Bs, wm, wn, g, tg, acc);
        __syncthreads();
    }
    tile_epilogue((float*)As, g_y1, 64, rowBase, n, wm, wn, g, tg, tid, 0, acc);
}

// ------ stage 2: y2 = sum_k h1t[neigh[:,k]] @ W2[k] — cp.async pipelined ----
__device__ __forceinline__ void g2_fill_async(uint32_t sA, uint32_t sB,
                                              const int* __restrict__ neigh,
                                              int rowBase, int n, int k, int tid) {
#pragma unroll
    for (int i = 0; i < 8; i++) {
        int fid = tid + 256 * i;
        int r = fid >> 4, j = fid & 15;
        int gr = rowBase + r;
        uint32_t dst = sA + (uint32_t)(r * A_STRIDE + j * 4) * 4u;
        const void* src = &g_h1t[0];
        int sz = 0;
        if (gr < n) {
            int idx = __ldg(&neigh[(size_t)gr * 27 + k]);
            src = &g_h1t[(size_t)idx * 64 + j * 4];
            sz = 16;
        }
        // src-size = 0 -> zero-fill (keeps padding rows zero for the stats)
        asm volatile("cp.async.cg.shared.global [%0], [%1], 16, %2;"
                     :: "r"(dst), "l"(src), "r"(sz));
    }
#pragma unroll
    for (int i = 0; i < 4; i++) {
        int fid = tid + 256 * i;
        int kr = fid >> 4, j = fid & 15;
        uint32_t dst = sB + (uint32_t)(kr * B_STRIDE + j * 4) * 4u;
        asm volatile("cp.async.cg.shared.global [%0], [%1], 16;"
                     :: "r"(dst), "l"(&g_W2t[((size_t)k * 64 + kr) * 64 + j * 4]));
    }
}

__global__ __launch_bounds__(256) void gemm2_tc_kernel(const int* __restrict__ neigh, int n) {
    extern __shared__ uint32_t smem[];
    uint32_t sb = (uint32_t)__cvta_generic_to_shared(smem);
    int tid = threadIdx.x, lid = tid & 31;
    int g = lid >> 2, tg = lid & 3;
    int wid = tid >> 5, wm = wid & 3, wn = wid >> 2;
    int rowBase = blockIdx.x * 128;

    float acc[2][4][4];
#pragma unroll
    for (int mt = 0; mt < 2; mt++)
#pragma unroll
        for (int nt = 0; nt < 4; nt++)
#pragma unroll
            for (int e = 0; e < 4; e++) acc[mt][nt][e] = 0.f;

    // prologue: prefetch tap 0 into stage 0
    g2_fill_async(sb, sb + AS_WORDS * 4, neigh, rowBase, n, 0, tid);
    asm volatile("cp.async.commit_group;" ::: "memory");

    for (int k = 0; k < 27; k++) {
        int cur = k & 1;
        if (k + 1 < 27) {
            int nxt = 1 - cur;
            // buffer nxt was consumed by MMA(k-1); trailing syncthreads of that
            // iteration makes the overwrite safe.
            g2_fill_async(sb + (uint32_t)nxt * STAGE_WORDS * 4,
                          sb + ((uint32_t)nxt * STAGE_WORDS + AS_WORDS) * 4,
                          neigh, rowBase, n, k + 1, tid);
            asm volatile("cp.async.commit_group;" ::: "memory");
            asm volatile("cp.async.wait_group 1;" ::: "memory");
        } else {
            asm volatile("cp.async.wait_group 0;" ::: "memory");
        }
        __syncthreads();
        tile_mma(smem + cur * STAGE_WORDS, smem + cur * STAGE_WORDS + AS_WORDS,
                 wm, wn, g, tg, acc);
        __syncthreads();
    }
    tile_epilogue((float*)smem, g_y2, 64, rowBase, n, wm, wn, g, tg, tid, 256, acc);
}

// ---------------- stage 3: y3 = h2t @ W3  (tf32 mma, grid.y = col slab) -----
__global__ __launch_bounds__(256) void gemm3_tc_kernel(int n) {
    extern __shared__ uint32_t smem[];
    uint32_t* As = smem;
    uint32_t* Bs = smem + AS_WORDS;
    int tid = threadIdx.x, lid = tid & 31;
    int g = lid >> 2, tg = lid & 3;
    int wid = tid >> 5, wm = wid & 3, wn = wid >> 2;
    int rowBase = blockIdx.x * 128;
    int colBase = blockIdx.y * 64;

    float acc[2][4][4];
#pragma unroll
    for (int mt = 0; mt < 2; mt++)
#pragma unroll
        for (int nt = 0; nt < 4; nt++)
#pragma unroll
            for (int e = 0; e < 4; e++) acc[mt][nt][e] = 0.f;

#pragma unroll
    for (int i = 0; i < 8; i++) {
        int fid = tid + 256 * i;
        int r = fid >> 4, j = fid & 15;
        int gr = rowBase + r;
        uint4 v = make_uint4(0u, 0u, 0u, 0u);
        if (gr < n) v = *(const uint4*)&g_h2t[(size_t)gr * 64 + j * 4];
        *(uint4*)&As[r * A_STRIDE + j * 4] = v;
    }
#pragma unroll
    for (int i = 0; i < 4; i++) {
        int fid = tid + 256 * i;
        int kr = fid >> 4, j = fid & 15;
        *(uint4*)&Bs[kr * B_STRIDE + j * 4] =
            *(const uint4*)&g_W3t[(size_t)kr * 256 + colBase + j * 4];
    }
    __syncthreads();
    tile_mma(As, Bs, wm, wn, g, tg, acc);
    __syncthreads();
    tile_epilogue((float*)As, g_y3 + colBase, 256, rowBase, n, wm, wn, g, tg, tid,
                  512 + colBase, acc);
}

// out = relu(bn3(y3) + x)   (BN3 scale/shift recomputed per block)
__global__ __launch_bounds__(256) void final_kernel(const float* __restrict__ x,
                                                    const float* __restrict__ gamma,
                                                    const float* __restrict__ beta,
                                                    float* __restrict__ out,
                                                    int n, float invN) {
    __shared__ float s_sc[256], s_sh[256];
    int tid = threadIdx.x;
    {
        float mean = g_sum[512 + tid] * invN;
        float var  = g_sumsq[512 + tid] * invN - mean * mean;
        float s = gamma[tid] * rsqrtf(var + EPS_BN);
        s_sc[tid] = s;
        s_sh[tid] = beta[tid] - mean * s;
    }
    __syncthreads();
    long i = (long)blockIdx.x * 256 + tid;
    long total4 = (long)n * 64;
    if (i < total4) {
        int c4 = (int)(i & 63) * 4;
        float4 y = *(const float4*)&g_y3[i * 4];
        float4 xi = *(const float4*)&x[i * 4];
        float4 s = *(const float4*)&s_sc[c4];
        float4 t = *(const float4*)&s_sh[c4];
        float4 o;
        o.x = fmaxf(fmaf(y.x, s.x, t.x) + xi.x, 0.f);
        o.y = fmaxf(fmaf(y.y, s.y, t.y) + xi.y, 0.f);
        o.z = fmaxf(fmaf(y.z, s.z, t.z) + xi.z, 0.f);
        o.w = fmaxf(fmaf(y.w, s.w, t.w) + xi.w, 0.f);
        *(float4*)&out[i * 4] = o;
    }
}

// ---------------------------------------------------------------------------
extern "C" void kernel_launch(void* const* d_in, const int* in_sizes, int n_in,
                              void* d_out, int out_size) {
    const float* x     = (const float*)d_in[0];
    const int*   neigh = (const int*)d_in[1];
    const float* W1 = (const float*)d_in[3];
    const float* g1 = (const float*)d_in[4];
    const float* b1 = (const float*)d_in[5];
    const float* W2 = (const float*)d_in[6];
    const float* g2 = (const float*)d_in[7];
    const float* b2 = (const float*)d_in[8];
    const float* W3 = (const float*)d_in[9];
    const float* g3 = (const float*)d_in[10];
    const float* b3 = (const float*)d_in[11];
    float* out = (float*)d_out;

    int n = in_sizes[0] / 256;
    int NB = (n + 127) / 128;
    float invN = 1.0f / (float)n;

    static bool attr_done = false;
    if (!attr_done) {
        cudaFuncSetAttribute(gemm1_tc_kernel, cudaFuncAttributeMaxDynamicSharedMemorySize, TC_SMEM);
        cudaFuncSetAttribute(gemm2_tc_kernel, cudaFuncAttributeMaxDynamicSharedMemorySize, TC_SMEM2);
        cudaFuncSetAttribute(gemm3_tc_kernel, cudaFuncAttributeMaxDynamicSharedMemorySize, TC_SMEM);
        attr_done = true;
    }

    int NH = (int)(((long)n * 16 + 255) / 256);

    prep_kernel<<<(110592 + 16384 + 255) / 256, 256>>>(W1, W2, W3);
    gemm1_tc_kernel<<<NB, 256, TC_SMEM>>>(x, n);
    prep_h_kernel<<<NH, 256>>>(g1, b1, 0, n, invN);
    gemm2_tc_kernel<<<NB, 256, TC_SMEM2>>>(neigh, n);
    prep_h_kernel<<<NH, 256>>>(g2, b2, 1, n, invN);
    gemm3_tc_kernel<<<dim3(NB, 4), 256, TC_SMEM>>>(n);
    final_kernel<<<(int)(((long)n * 64 + 255) / 256), 256>>>(x, g3, b3, out, n, invN);
}

// round 16
// speedup vs baseline: 3.9332x; 1.7626x over previous
#include <cuda_runtime.h>
#include <cuda_fp16.h>
#include <cstdint>

#define EPS_BN 1e-3f
#define MAXN 200000

// ---------------- scratch (__device__ globals; no allocation allowed) --------
__device__ __align__(16) float  g_y1[MAXN * 64];      // stage-1 pre-BN output
__device__ __align__(16) __half g_h1h[MAXN * 64];     // fp16(relu(bn1(y1)))
__device__ __align__(16) float  g_y2[MAXN * 64];      // stage-2 pre-BN output
__device__ __align__(16) __half g_h2h[MAXN * 64];     // fp16(relu(bn2(y2)))
__device__ __align__(16) float  g_y3[MAXN * 256];     // stage-3 pre-BN output
__device__ __align__(16) __half g_W1h[256 * 64];      // fp16 W1 [n][k=256] (transposed)
__device__ __align__(16) __half g_W2h[27 * 64 * 64];  // fp16 W2 [tap][n=d][k=c] (transposed)
__device__ __align__(16) __half g_W3h[256 * 64];      // fp16 W3 [n][k=64] (transposed)
__device__ __align__(16) float g_sum[3 * 256];
__device__ __align__(16) float g_sumsq[3 * 256];

// ---------------------------- PTX helpers ------------------------------------
__device__ __forceinline__ void ldsm4(uint32_t& r0, uint32_t& r1, uint32_t& r2,
                                      uint32_t& r3, uint32_t addr) {
    asm volatile("ldmatrix.sync.aligned.m8n8.x4.shared.b16 {%0,%1,%2,%3}, [%4];"
                 : "=r"(r0), "=r"(r1), "=r"(r2), "=r"(r3) : "r"(addr));
}
// D += A(16x16 f16, row) * B(16x8 f16, col), fp32 accumulate
__device__ __forceinline__ void mma_h(float* d, const uint32_t* a, uint32_t b0, uint32_t b1) {
    asm volatile(
        "mma.sync.aligned.m16n8k16.row.col.f32.f16.f16.f32 "
        "{%0,%1,%2,%3}, {%4,%5,%6,%7}, {%8,%9}, {%0,%1,%2,%3};"
        : "+f"(d[0]), "+f"(d[1]), "+f"(d[2]), "+f"(d[3])
        : "r"(a[0]), "r"(a[1]), "r"(a[2]), "r"(a[3]), "r"(b0), "r"(b1));
}

// Smem tile geometry (halves): A = 128 rows x 72-stride (64 used)
//                              B =  64 n-rows x 72-stride (64 used), [n][k]
#define H_STRIDE 72
#define A_BYTES  (128 * H_STRIDE * 2)   // 18432
#define B_BYTES  (64 * H_STRIDE * 2)    // 9216
#define STAGE_B  (A_BYTES + B_BYTES)    // 27648
#define RED_BYTES (128 * 68 * 4)        // 34816 (fp32 reduction reuse)
#define SM1 RED_BYTES                   // single-stage kernels
#define SM2 (2 * STAGE_B)               // 55296, gemm2 double-buffered (>= RED_BYTES)

// Warp-tile MMA over one 128x64(A) x 64x64(B[n][k]) smem tile pair, fp16.
__device__ __forceinline__ void tile_mma_h(uint32_t sA, uint32_t sB, int wm, int wn,
                                           int lane, float acc[2][4][4]) {
    int q = lane >> 3, rr = lane & 7;
    int qc = (q >> 1) * 8;   // half-column offset within 16-wide k block
    int qr = (q & 1) * 8;    // row offset within 16-row block
    uint32_t aA0 = sA + (uint32_t)(((wm * 32 + qr + rr) * H_STRIDE + qc) * 2);
    uint32_t aA1 = aA0 + 16u * H_STRIDE * 2u;
    uint32_t aB0 = sB + (uint32_t)(((wn * 32 + qr + rr) * H_STRIDE + qc) * 2);
    uint32_t aB1 = aB0 + 16u * H_STRIDE * 2u;
#pragma unroll
    for (int kt = 0; kt < 4; kt++) {
        uint32_t a0[4], a1[4], b0[4], b1[4];
        ldsm4(a0[0], a0[1], a0[2], a0[3], aA0 + kt * 32);
        ldsm4(a1[0], a1[1], a1[2], a1[3], aA1 + kt * 32);
        ldsm4(b0[0], b0[1], b0[2], b0[3], aB0 + kt * 32);
        ldsm4(b1[0], b1[1], b1[2], b1[3], aB1 + kt * 32);
        mma_h(acc[0][0], a0, b0[0], b0[2]);
        mma_h(acc[0][1], a0, b0[1], b0[3]);
        mma_h(acc[0][2], a0, b1[0], b1[2]);
        mma_h(acc[0][3], a0, b1[1], b1[3]);
        mma_h(acc[1][0], a1, b0[0], b0[2]);
        mma_h(acc[1][1], a1, b0[1], b0[3]);
        mma_h(acc[1][2], a1, b1[0], b1[2]);
        mma_h(acc[1][3], a1, b1[1], b1[3]);
    }
}

// Epilogue: acc -> red smem + gmem slab, then column sum/sumsq -> atomicAdd.
__device__ __forceinline__ void tile_epilogue(float* red, float* outBase, size_t outStride,
                                              int rowBase, int n, int wm, int wn,
                                              int g, int tg, int tid, int statBase,
                                              float acc[2][4][4]) {
#pragma unroll
    for (int mt = 0; mt < 2; mt++) {
        int r = wm * 32 + mt * 16 + g;
#pragma unroll
        for (int nt = 0; nt < 4; nt++) {
            int c = wn * 32 + nt * 8 + tg * 2;
            red[r * 68 + c]           = acc[mt][nt][0];
            red[r * 68 + c + 1]       = acc[mt][nt][1];
            red[(r + 8) * 68 + c]     = acc[mt][nt][2];
            red[(r + 8) * 68 + c + 1] = acc[mt][nt][3];
            int gr = rowBase + r;
            if (gr < n)
                *(float2*)&outBase[(size_t)gr * outStride + c] =
                    make_float2(acc[mt][nt][0], acc[mt][nt][1]);
            if (gr + 8 < n)
                *(float2*)&outBase[(size_t)(gr + 8) * outStride + c] =
                    make_float2(acc[mt][nt][2], acc[mt][nt][3]);
        }
    }
    __syncthreads();
    if (tid < 64) {
        float s = 0.f, q = 0.f;
#pragma unroll 8
        for (int r = 0; r < 128; r++) {
            float v = red[r * 68 + tid];
            s += v; q += v * v;
        }
        atomicAdd(&g_sum[statBase + tid], s);
        atomicAdd(&g_sumsq[statBase + tid], q);
    }
}

// ---------------------------------------------------------------------------
// Fused: zero stats + fp16 weight transposes.
__global__ void prep_kernel(const float* __restrict__ W1,
                            const float* __restrict__ W2,
                            const float* __restrict__ W3) {
    int i = blockIdx.x * 256 + threadIdx.x;
    if (i < 768) { g_sum[i] = 0.f; g_sumsq[i] = 0.f; }
    if (i < 16384) {            // W1h[n][k]: n = i>>8, k = i&255
        int nn = i >> 8, k = i & 255;
        g_W1h[i] = __float2half_rn(W1[k * 64 + nn]);
    }
    if (i < 110592) {           // W2h[t][d][c] = W2[t][c][d]
        int t = i >> 12, d = (i >> 6) & 63, c = i & 63;
        g_W2h[i] = __float2half_rn(W2[(t << 12) + (c << 6) + d]);
    }
    if (i >= 16384 && i < 32768) {  // W3h[n][k]: j = i-16384, n = j>>6, k = j&63
        int j = i - 16384;
        int nn = j >> 6, k = j & 63;
        g_W3h[j] = __float2half_rn(W3[k * 256 + nn]);
    }
}

// h{1,2}h = fp16(relu(bn(y))) — BN scale/shift recomputed per block.
__global__ __launch_bounds__(256) void prep_h_kernel(const float* __restrict__ gamma,
                                                     const float* __restrict__ beta,
                                                     int stage, int n, float invN) {
    __shared__ float s_sc[64], s_sh[64];
    const float* __restrict__ y = (stage == 0) ? g_y1 : g_y2;
    __half* __restrict__ ht     = (stage == 0) ? g_h1h : g_h2h;
    int tid = threadIdx.x;
    if (tid < 64) {
        float mean = g_sum[stage * 256 + tid] * invN;
        float var  = g_sumsq[stage * 256 + tid] * invN - mean * mean;
        float s = gamma[tid] * rsqrtf(var + EPS_BN);
        s_sc[tid] = s;
        s_sh[tid] = beta[tid] - mean * s;
    }
    __syncthreads();
    long i = (long)blockIdx.x * 256 + tid;   // float4 index
    long total4 = (long)n * 16;
    if (i < total4) {
        int c4 = (int)(i & 15) * 4;
        float4 v = *(const float4*)&y[i * 4];
        float4 s = *(const float4*)&s_sc[c4];
        float4 t = *(const float4*)&s_sh[c4];
        __half2 h01 = __floats2half2_rn(fmaxf(fmaf(v.x, s.x, t.x), 0.f),
                                        fmaxf(fmaf(v.y, s.y, t.y), 0.f));
        __half2 h23 = __floats2half2_rn(fmaxf(fmaf(v.z, s.z, t.z), 0.f),
                                        fmaxf(fmaf(v.w, s.w, t.w), 0.f));
        uint2 o = make_uint2(*(uint32_t*)&h01, *(uint32_t*)&h23);
        *(uint2*)&ht[i * 4] = o;
    }
}

// ---------------- stage 1: y1 = x @ W1  (fp16 mma, K=256 in 4 chunks) -------
__global__ __launch_bounds__(256) void gemm1_tc_kernel(const float* __restrict__ x, int n) {
    extern __shared__ char smem[];
    uint32_t sA = (uint32_t)__cvta_generic_to_shared(smem);
    uint32_t sB = sA + A_BYTES;
    __half* As = (__half*)smem;
    __half* Bs = (__half*)(smem + A_BYTES);
    int tid = threadIdx.x, lid = tid & 31;
    int g = lid >> 2, tg = lid & 3;
    int wid = tid >> 5, wm = wid & 3, wn = wid >> 2;
    int rowBase = blockIdx.x * 128;

    float acc[2][4][4];
#pragma unroll
    for (int mt = 0; mt < 2; mt++)
#pragma unroll
        for (int nt = 0; nt < 4; nt++)
#pragma unroll
            for (int e = 0; e < 4; e++) acc[mt][nt][e] = 0.f;

    for (int k0 = 0; k0 < 256; k0 += 64) {
        // A fill: 128 rows x 64 halves; each thread converts 8 floats -> 8 halves
#pragma unroll
        for (int i = 0; i < 4; i++) {
            int fid = tid + 256 * i;
            int r = fid >> 3, j = fid & 7;
            int gr = rowBase + r;
            uint2 o = make_uint2(0u, 0u);
            uint2 o2 = make_uint2(0u, 0u);
            if (gr < n) {
                const float4* xp = (const float4*)&x[(size_t)gr * 256 + k0 + j * 8];
                float4 v0 = xp[0], v1 = xp[1];
                __half2 h0 = __floats2half2_rn(v0.x, v0.y);
                __half2 h1 = __floats2half2_rn(v0.z, v0.w);
                __half2 h2 = __floats2half2_rn(v1.x, v1.y);
                __half2 h3 = __floats2half2_rn(v1.z, v1.w);
                o  = make_uint2(*(uint32_t*)&h0, *(uint32_t*)&h1);
                o2 = make_uint2(*(uint32_t*)&h2, *(uint32_t*)&h3);
            }
            uint4 u = make_uint4(o.x, o.y, o2.x, o2.y);
            *(uint4*)((char*)As + r * 144 + j * 16) = u;
        }
        // B fill: W1h[n][k0..k0+63]
#pragma unroll
        for (int i = 0; i < 2; i++) {
            int fid = tid + 256 * i;
            int r = fid >> 3, j = fid & 7;
            *(uint4*)((char*)Bs + r * 144 + j * 16) =
                *(const uint4*)&g_W1h[(size_t)r * 256 + k0 + j * 8];
        }
        __syncthreads();
        tile_mma_h(sA, sB, wm, wn, lid, acc);
        __syncthreads();
    }
    tile_epilogue((float*)smem, g_y1, 64, rowBase, n, wm, wn, g, tg, tid, 0, acc);
}

// ------ stage 2: y2 = sum_k h1h[neigh[:,k]] @ W2[k] — cp.async pipelined ----
__device__ __forceinline__ void g2_fill_async(uint32_t sA, uint32_t sB,
                                              const int* __restrict__ neigh,
                                              int rowBase, int n, int k, int tid) {
#pragma unroll
    for (int i = 0; i < 4; i++) {
        int fid = tid + 256 * i;      // 0..1023: 128 rows x 8 chunks of 16B
        int r = fid >> 3, j = fid & 7;
        int gr = rowBase + r;
        uint32_t dst = sA + (uint32_t)(r * 144 + j * 16);
        const void* src = &g_h1h[0];
        int sz = 0;
        if (gr < n) {
            int idx = __ldg(&neigh[(size_t)gr * 27 + k]);
            src = &g_h1h[(size_t)idx * 64 + j * 8];
            sz = 16;
        }
        asm volatile("cp.async.cg.shared.global [%0], [%1], 16, %2;"
                     :: "r"(dst), "l"(src), "r"(sz));
    }
#pragma unroll
    for (int i = 0; i < 2; i++) {
        int fid = tid + 256 * i;      // 0..511: 64 n-rows x 8 chunks
        int r = fid >> 3, j = fid & 7;
        uint32_t dst = sB + (uint32_t)(r * 144 + j * 16);
        asm volatile("cp.async.cg.shared.global [%0], [%1], 16;"
                     :: "r"(dst), "l"(&g_W2h[(size_t)k * 4096 + r * 64 + j * 8]));
    }
}

__global__ __launch_bounds__(256, 3) void gemm2_tc_kernel(const int* __restrict__ neigh, int n) {
    extern __shared__ char smem[];
    uint32_t sb = (uint32_t)__cvta_generic_to_shared(smem);
    int tid = threadIdx.x, lid = tid & 31;
    int g = lid >> 2, tg = lid & 3;
    int wid = tid >> 5, wm = wid & 3, wn = wid >> 2;
    int rowBase = blockIdx.x * 128;

    float acc[2][4][4];
#pragma unroll
    for (int mt = 0; mt < 2; mt++)
#pragma unroll
        for (int nt = 0; nt < 4; nt++)
#pragma unroll
            for (int e = 0; e < 4; e++) acc[mt][nt][e] = 0.f;

    // prologue: prefetch tap 0 into stage 0
    g2_fill_async(sb, sb + A_BYTES, neigh, rowBase, n, 0, tid);
    asm volatile("cp.async.commit_group;" ::: "memory");

    for (int k = 0; k < 27; k++) {
        int cur = k & 1;
        if (k + 1 < 27) {
            int nxt = 1 - cur;
            g2_fill_async(sb + (uint32_t)nxt * STAGE_B,
                          sb + (uint32_t)nxt * STAGE_B + A_BYTES,
                          neigh, rowBase, n, k + 1, tid);
            asm volatile("cp.async.commit_group;" ::: "memory");
            asm volatile("cp.async.wait_group 1;" ::: "memory");
        } else {
            asm volatile("cp.async.wait_group 0;" ::: "memory");
        }
        __syncthreads();
        tile_mma_h(sb + (uint32_t)cur * STAGE_B,
                   sb + (uint32_t)cur * STAGE_B + A_BYTES, wm, wn, lid, acc);
        __syncthreads();
    }
    tile_epilogue((float*)smem, g_y2, 64, rowBase, n, wm, wn, g, tg, tid, 256, acc);
}

// ---------------- stage 3: y3 = h2h @ W3  (fp16 mma, grid.y = col slab) -----
__global__ __launch_bounds__(256) void gemm3_tc_kernel(int n) {
    extern __shared__ char smem[];
    uint32_t sA = (uint32_t)__cvta_generic_to_shared(smem);
    uint32_t sB = sA + A_BYTES;
    __half* As = (__half*)smem;
    __half* Bs = (__half*)(smem + A_BYTES);
    int tid = threadIdx.x, lid = tid & 31;
    int g = lid >> 2, tg = lid & 3;
    int wid = tid >> 5, wm = wid & 3, wn = wid >> 2;
    int rowBase = blockIdx.x * 128;
    int colBase = blockIdx.y * 64;

    float acc[2][4][4];
#pragma unroll
    for (int mt = 0; mt < 2; mt++)
#pragma unroll
        for (int nt = 0; nt < 4; nt++)
#pragma unroll
            for (int e = 0; e < 4; e++) acc[mt][nt][e] = 0.f;

#pragma unroll
    for (int i = 0; i < 4; i++) {
        int fid = tid + 256 * i;
        int r = fid >> 3, j = fid & 7;
        int gr = rowBase + r;
        uint4 v = make_uint4(0u, 0u, 0u, 0u);
        if (gr < n) v = *(const uint4*)&g_h2h[(size_t)gr * 64 + j * 8];
        *(uint4*)((char*)As + r * 144 + j * 16) = v;
    }
#pragma unroll
    for (int i = 0; i < 2; i++) {
        int fid = tid + 256 * i;
        int r = fid >> 3, j = fid & 7;
        *(uint4*)((char*)Bs + r * 144 + j * 16) =
            *(const uint4*)&g_W3h[(size_t)(colBase + r) * 64 + j * 8];
    }
    __syncthreads();
    tile_mma_h(sA, sB, wm, wn, lid, acc);
    __syncthreads();
    tile_epilogue((float*)smem, g_y3 + colBase, 256, rowBase, n, wm, wn, g, tg, tid,
                  512 + colBase, acc);
}

// out = relu(bn3(y3) + x)   (BN3 scale/shift recomputed per block)
__global__ __launch_bounds__(256) void final_kernel(const float* __restrict__ x,
                                                    const float* __restrict__ gamma,
                                                    const float* __restrict__ beta,
                                                    float* __restrict__ out,
                                                    int n, float invN) {
    __shared__ float s_sc[256], s_sh[256];
    int tid = threadIdx.x;
    {
        float mean = g_sum[512 + tid] * invN;
        float var  = g_sumsq[512 + tid] * invN - mean * mean;
        float s = gamma[tid] * rsqrtf(var + EPS_BN);
        s_sc[tid] = s;
        s_sh[tid] = beta[tid] - mean * s;
    }
    __syncthreads();
    long i = (long)blockIdx.x * 256 + tid;
    long total4 = (long)n * 64;
    if (i < total4) {
        int c4 = (int)(i & 63) * 4;
        float4 y = *(const float4*)&g_y3[i * 4];
        float4 xi = *(const float4*)&x[i * 4];
        float4 s = *(const float4*)&s_sc[c4];
        float4 t = *(const float4*)&s_sh[c4];
        float4 o;
        o.x = fmaxf(fmaf(y.x, s.x, t.x) + xi.x, 0.f);
        o.y = fmaxf(fmaf(y.y, s.y, t.y) + xi.y, 0.f);
        o.z = fmaxf(fmaf(y.z, s.z, t.z) + xi.z, 0.f);
        o.w = fmaxf(fmaf(y.w, s.w, t.w) + xi.w, 0.f);
        *(float4*)&out[i * 4] = o;
    }
}

// ---------------------------------------------------------------------------
extern "C" void kernel_launch(void* const* d_in, const int* in_sizes, int n_in,
                              void* d_out, int out_size) {
    const float* x     = (const float*)d_in[0];
    const int*   neigh = (const int*)d_in[1];
    const float* W1 = (const float*)d_in[3];
    const float* g1 = (const float*)d_in[4];
    const float* b1 = (const float*)d_in[5];
    const float* W2 = (const float*)d_in[6];
    const float* g2 = (const float*)d_in[7];
    const float* b2 = (const float*)d_in[8];
    const float* W3 = (const float*)d_in[9];
    const float* g3 = (const float*)d_in[10];
    const float* b3 = (const float*)d_in[11];
    float* out = (float*)d_out;

    int n = in_sizes[0] / 256;
    int NB = (n + 127) / 128;
    float invN = 1.0f / (float)n;

    static bool attr_done = false;
    if (!attr_done) {
        cudaFuncSetAttribute(gemm1_tc_kernel, cudaFuncAttributeMaxDynamicSharedMemorySize, SM1);
        cudaFuncSetAttribute(gemm2_tc_kernel, cudaFuncAttributeMaxDynamicSharedMemorySize, SM2);
        cudaFuncSetAttribute(gemm3_tc_kernel, cudaFuncAttributeMaxDynamicSharedMemorySize, SM1);
        attr_done = true;
    }

    int NH = (int)(((long)n * 16 + 255) / 256);

    prep_kernel<<<(110592 + 255) / 256, 256>>>(W1, W2, W3);
    gemm1_tc_kernel<<<NB, 256, SM1>>>(x, n);
    prep_h_kernel<<<NH, 256>>>(g1, b1, 0, n, invN);
    gemm2_tc_kernel<<<NB, 256, SM2>>>(neigh, n);
    prep_h_kernel<<<NH, 256>>>(g2, b2, 1, n, invN);
    gemm3_tc_kernel<<<dim3(NB, 4), 256, SM1>>>(n);
    final_kernel<<<(int)(((long)n * 64 + 255) / 256), 256>>>(x, g3, b3, out, n, invN);
}

// round 17
// speedup vs baseline: 4.0521x; 1.0302x over previous
#include <cuda_runtime.h>
#include <cuda_fp16.h>
#include <cstdint>

#define EPS_BN 1e-3f
#define MAXN 200000

// ---------------- scratch (__device__ globals; no allocation allowed) --------
__device__ __align__(16) float  g_y1[MAXN * 64];      // stage-1 pre-BN output
__device__ __align__(16) __half g_h1h[MAXN * 64];     // fp16(relu(bn1(y1)))
__device__ __align__(16) float  g_y2[MAXN * 64];      // stage-2 pre-BN output
__device__ __align__(16) __half g_h2h[MAXN * 64];     // fp16(relu(bn2(y2)))
__device__ __align__(16) __half g_y3h[MAXN * 256];    // stage-3 pre-BN output (fp16 store)
__device__ __align__(16) __half g_W1h[256 * 64];      // fp16 W1 [n][k=256] (transposed)
__device__ __align__(16) __half g_W2h[27 * 64 * 64];  // fp16 W2 [tap][n=d][k=c] (transposed)
__device__ __align__(16) __half g_W3h[256 * 64];      // fp16 W3 [n][k=64] (transposed)
__device__ __align__(16) float g_sum[3 * 256];
__device__ __align__(16) float g_sumsq[3 * 256];

// ---------------------------- PTX helpers ------------------------------------
__device__ __forceinline__ void ldsm4(uint32_t& r0, uint32_t& r1, uint32_t& r2,
                                      uint32_t& r3, uint32_t addr) {
    asm volatile("ldmatrix.sync.aligned.m8n8.x4.shared.b16 {%0,%1,%2,%3}, [%4];"
                 : "=r"(r0), "=r"(r1), "=r"(r2), "=r"(r3) : "r"(addr));
}
// D += A(16x16 f16, row) * B(16x8 f16, col), fp32 accumulate
__device__ __forceinline__ void mma_h(float* d, const uint32_t* a, uint32_t b0, uint32_t b1) {
    asm volatile(
        "mma.sync.aligned.m16n8k16.row.col.f32.f16.f16.f32 "
        "{%0,%1,%2,%3}, {%4,%5,%6,%7}, {%8,%9}, {%0,%1,%2,%3};"
        : "+f"(d[0]), "+f"(d[1]), "+f"(d[2]), "+f"(d[3])
        : "r"(a[0]), "r"(a[1]), "r"(a[2]), "r"(a[3]), "r"(b0), "r"(b1));
}

// Smem tile geometry (halves): A = 128 rows x 72-stride (64 used)
//                              B =  64 n-rows x 72-stride (64 used), [n][k]
#define H_STRIDE 72
#define A_BYTES  (128 * H_STRIDE * 2)   // 18432
#define B_BYTES  (64 * H_STRIDE * 2)    // 9216
#define STAGE_B  (A_BYTES + B_BYTES)    // 27648
#define RED_BYTES (128 * 68 * 4)        // 34816 (fp32 reduction reuse)
#define SM1 RED_BYTES                   // single-stage kernels
#define SM2 (2 * STAGE_B)               // 55296, gemm2 double-buffered (>= RED_BYTES)

// Warp-tile MMA over one 128x64(A) x 64x64(B[n][k]) smem tile pair, fp16.
__device__ __forceinline__ void tile_mma_h(uint32_t sA, uint32_t sB, int wm, int wn,
                                           int lane, float acc[2][4][4]) {
    int q = lane >> 3, rr = lane & 7;
    int qc = (q >> 1) * 8;   // half-column offset within 16-wide k block
    int qr = (q & 1) * 8;    // row offset within 16-row block
    uint32_t aA0 = sA + (uint32_t)(((wm * 32 + qr + rr) * H_STRIDE + qc) * 2);
    uint32_t aA1 = aA0 + 16u * H_STRIDE * 2u;
    uint32_t aB0 = sB + (uint32_t)(((wn * 32 + qr + rr) * H_STRIDE + qc) * 2);
    uint32_t aB1 = aB0 + 16u * H_STRIDE * 2u;
#pragma unroll
    for (int kt = 0; kt < 4; kt++) {
        uint32_t a0[4], a1[4], b0[4], b1[4];
        ldsm4(a0[0], a0[1], a0[2], a0[3], aA0 + kt * 32);
        ldsm4(a1[0], a1[1], a1[2], a1[3], aA1 + kt * 32);
        ldsm4(b0[0], b0[1], b0[2], b0[3], aB0 + kt * 32);
        ldsm4(b1[0], b1[1], b1[2], b1[3], aB1 + kt * 32);
        mma_h(acc[0][0], a0, b0[0], b0[2]);
        mma_h(acc[0][1], a0, b0[1], b0[3]);
        mma_h(acc[0][2], a0, b1[0], b1[2]);
        mma_h(acc[0][3], a0, b1[1], b1[3]);
        mma_h(acc[1][0], a1, b0[0], b0[2]);
        mma_h(acc[1][1], a1, b0[1], b0[3]);
        mma_h(acc[1][2], a1, b1[0], b1[2]);
        mma_h(acc[1][3], a1, b1[1], b1[3]);
    }
}

// Epilogue (fp32 out): acc -> red smem + gmem slab, then column stats atomicAdd.
__device__ __forceinline__ void tile_epilogue(float* red, float* outBase, size_t outStride,
                                              int rowBase, int n, int wm, int wn,
                                              int g, int tg, int tid, int statBase,
                                              float acc[2][4][4]) {
#pragma unroll
    for (int mt = 0; mt < 2; mt++) {
        int r = wm * 32 + mt * 16 + g;
#pragma unroll
        for (int nt = 0; nt < 4; nt++) {
            int c = wn * 32 + nt * 8 + tg * 2;
            red[r * 68 + c]           = acc[mt][nt][0];
            red[r * 68 + c + 1]       = acc[mt][nt][1];
            red[(r + 8) * 68 + c]     = acc[mt][nt][2];
            red[(r + 8) * 68 + c + 1] = acc[mt][nt][3];
            int gr = rowBase + r;
            if (gr < n)
                *(float2*)&outBase[(size_t)gr * outStride + c] =
                    make_float2(acc[mt][nt][0], acc[mt][nt][1]);
            if (gr + 8 < n)
                *(float2*)&outBase[(size_t)(gr + 8) * outStride + c] =
                    make_float2(acc[mt][nt][2], acc[mt][nt][3]);
        }
    }
    __syncthreads();
    if (tid < 64) {
        float s = 0.f, q = 0.f;
#pragma unroll 8
        for (int r = 0; r < 128; r++) {
            float v = red[r * 68 + tid];
            s += v; q += v * v;
        }
        atomicAdd(&g_sum[statBase + tid], s);
        atomicAdd(&g_sumsq[statBase + tid], q);
    }
}

// Epilogue (fp16 out, for y3): stats from fp32 acc, stored elements rounded.
__device__ __forceinline__ void tile_epilogue_h(float* red, __half* outBase, size_t outStride,
                                                int rowBase, int n, int wm, int wn,
                                                int g, int tg, int tid, int statBase,
                                                float acc[2][4][4]) {
#pragma unroll
    for (int mt = 0; mt < 2; mt++) {
        int r = wm * 32 + mt * 16 + g;
#pragma unroll
        for (int nt = 0; nt < 4; nt++) {
            int c = wn * 32 + nt * 8 + tg * 2;
            red[r * 68 + c]           = acc[mt][nt][0];
            red[r * 68 + c + 1]       = acc[mt][nt][1];
            red[(r + 8) * 68 + c]     = acc[mt][nt][2];
            red[(r + 8) * 68 + c + 1] = acc[mt][nt][3];
            int gr = rowBase + r;
            if (gr < n) {
                __half2 h = __floats2half2_rn(acc[mt][nt][0], acc[mt][nt][1]);
                *(uint32_t*)&outBase[(size_t)gr * outStride + c] = *(uint32_t*)&h;
            }
            if (gr + 8 < n) {
                __half2 h = __floats2half2_rn(acc[mt][nt][2], acc[mt][nt][3]);
                *(uint32_t*)&outBase[(size_t)(gr + 8) * outStride + c] = *(uint32_t*)&h;
            }
        }
    }
    __syncthreads();
    if (tid < 64) {
        float s = 0.f, q = 0.f;
#pragma unroll 8
        for (int r = 0; r < 128; r++) {
            float v = red[r * 68 + tid];
            s += v; q += v * v;
        }
        atomicAdd(&g_sum[statBase + tid], s);
        atomicAdd(&g_sumsq[statBase + tid], q);
    }
}

// ---------------------------------------------------------------------------
// Fused: zero stats + fp16 weight transposes.
__global__ void prep_kernel(const float* __restrict__ W1,
                            const float* __restrict__ W2,
                            const float* __restrict__ W3) {
    int i = blockIdx.x * 256 + threadIdx.x;
    if (i < 768) { g_sum[i] = 0.f; g_sumsq[i] = 0.f; }
    if (i < 16384) {            // W1h[n][k]: n = i>>8, k = i&255
        int nn = i >> 8, k = i & 255;
        g_W1h[i] = __float2half_rn(W1[k * 64 + nn]);
    }
    if (i < 110592) {           // W2h[t][d][c] = W2[t][c][d]
        int t = i >> 12, d = (i >> 6) & 63, c = i & 63;
        g_W2h[i] = __float2half_rn(W2[(t << 12) + (c << 6) + d]);
    }
    if (i >= 16384 && i < 32768) {  // W3h[n][k]: j = i-16384, n = j>>6, k = j&63
        int j = i - 16384;
        int nn = j >> 6, k = j & 63;
        g_W3h[j] = __float2half_rn(W3[k * 256 + nn]);
    }
}

// h{1,2}h = fp16(relu(bn(y))) — BN scale/shift recomputed per block.
__global__ __launch_bounds__(256) void prep_h_kernel(const float* __restrict__ gamma,
                                                     const float* __restrict__ beta,
                                                     int stage, int n, float invN) {
    __shared__ float s_sc[64], s_sh[64];
    const float* __restrict__ y = (stage == 0) ? g_y1 : g_y2;
    __half* __restrict__ ht     = (stage == 0) ? g_h1h : g_h2h;
    int tid = threadIdx.x;
    if (tid < 64) {
        float mean = g_sum[stage * 256 + tid] * invN;
        float var  = g_sumsq[stage * 256 + tid] * invN - mean * mean;
        float s = gamma[tid] * rsqrtf(var + EPS_BN);
        s_sc[tid] = s;
        s_sh[tid] = beta[tid] - mean * s;
    }
    __syncthreads();
    long i = (long)blockIdx.x * 256 + tid;   // float4 index
    long total4 = (long)n * 16;
    if (i < total4) {
        int c4 = (int)(i & 15) * 4;
        float4 v = *(const float4*)&y[i * 4];
        float4 s = *(const float4*)&s_sc[c4];
        float4 t = *(const float4*)&s_sh[c4];
        __half2 h01 = __floats2half2_rn(fmaxf(fmaf(v.x, s.x, t.x), 0.f),
                                        fmaxf(fmaf(v.y, s.y, t.y), 0.f));
        __half2 h23 = __floats2half2_rn(fmaxf(fmaf(v.z, s.z, t.z), 0.f),
                                        fmaxf(fmaf(v.w, s.w, t.w), 0.f));
        uint2 o = make_uint2(*(uint32_t*)&h01, *(uint32_t*)&h23);
        *(uint2*)&ht[i * 4] = o;
    }
}

// ---------------- stage 1: y1 = x @ W1  (fp16 mma, K=256 in 4 chunks) -------
__global__ __launch_bounds__(256) void gemm1_tc_kernel(const float* __restrict__ x, int n) {
    extern __shared__ char smem[];
    uint32_t sA = (uint32_t)__cvta_generic_to_shared(smem);
    uint32_t sB = sA + A_BYTES;
    __half* As = (__half*)smem;
    __half* Bs = (__half*)(smem + A_BYTES);
    int tid = threadIdx.x, lid = tid & 31;
    int g = lid >> 2, tg = lid & 3;
    int wid = tid >> 5, wm = wid & 3, wn = wid >> 2;
    int rowBase = blockIdx.x * 128;

    float acc[2][4][4];
#pragma unroll
    for (int mt = 0; mt < 2; mt++)
#pragma unroll
        for (int nt = 0; nt < 4; nt++)
#pragma unroll
            for (int e = 0; e < 4; e++) acc[mt][nt][e] = 0.f;

    for (int k0 = 0; k0 < 256; k0 += 64) {
        // A fill: 128 rows x 64 halves; each thread converts 8 floats -> 8 halves
#pragma unroll
        for (int i = 0; i < 4; i++) {
            int fid = tid + 256 * i;
            int r = fid >> 3, j = fid & 7;
            int gr = rowBase + r;
            uint2 o = make_uint2(0u, 0u);
            uint2 o2 = make_uint2(0u, 0u);
            if (gr < n) {
                const float4* xp = (const float4*)&x[(size_t)gr * 256 + k0 + j * 8];
                float4 v0 = xp[0], v1 = xp[1];
                __half2 h0 = __floats2half2_rn(v0.x, v0.y);
                __half2 h1 = __floats2half2_rn(v0.z, v0.w);
                __half2 h2 = __floats2half2_rn(v1.x, v1.y);
                __half2 h3 = __floats2half2_rn(v1.z, v1.w);
                o  = make_uint2(*(uint32_t*)&h0, *(uint32_t*)&h1);
                o2 = make_uint2(*(uint32_t*)&h2, *(uint32_t*)&h3);
            }
            uint4 u = make_uint4(o.x, o.y, o2.x, o2.y);
            *(uint4*)((char*)As + r * 144 + j * 16) = u;
        }
        // B fill: W1h[n][k0..k0+63]
#pragma unroll
        for (int i = 0; i < 2; i++) {
            int fid = tid + 256 * i;
            int r = fid >> 3, j = fid & 7;
            *(uint4*)((char*)Bs + r * 144 + j * 16) =
                *(const uint4*)&g_W1h[(size_t)r * 256 + k0 + j * 8];
        }
        __syncthreads();
        tile_mma_h(sA, sB, wm, wn, lid, acc);
        __syncthreads();
    }
    tile_epilogue((float*)smem, g_y1, 64, rowBase, n, wm, wn, g, tg, tid, 0, acc);
}

// ------ stage 2: y2 = sum_k h1h[neigh[:,k]] @ W2[k] — cp.async pipelined ----
__device__ __forceinline__ void g2_fill_async(uint32_t sA, uint32_t sB,
                                              const int* __restrict__ neigh,
                                              int rowBase, int n, int k, int tid) {
#pragma unroll
    for (int i = 0; i < 4; i++) {
        int fid = tid + 256 * i;      // 0..1023: 128 rows x 8 chunks of 16B
        int r = fid >> 3, j = fid & 7;
        int gr = rowBase + r;
        uint32_t dst = sA + (uint32_t)(r * 144 + j * 16);
        const void* src = &g_h1h[0];
        int sz = 0;
        if (gr < n) {
            int idx = __ldg(&neigh[(size_t)gr * 27 + k]);
            src = &g_h1h[(size_t)idx * 64 + j * 8];
            sz = 16;
        }
        asm volatile("cp.async.cg.shared.global [%0], [%1], 16, %2;"
                     :: "r"(dst), "l"(src), "r"(sz));
    }
#pragma unroll
    for (int i = 0; i < 2; i++) {
        int fid = tid + 256 * i;      // 0..511: 64 n-rows x 8 chunks
        int r = fid >> 3, j = fid & 7;
        uint32_t dst = sB + (uint32_t)(r * 144 + j * 16);
        asm volatile("cp.async.cg.shared.global [%0], [%1], 16;"
                     :: "r"(dst), "l"(&g_W2h[(size_t)k * 4096 + r * 64 + j * 8]));
    }
}

__global__ __launch_bounds__(256, 4) void gemm2_tc_kernel(const int* __restrict__ neigh, int n) {
    extern __shared__ char smem[];
    uint32_t sb = (uint32_t)__cvta_generic_to_shared(smem);
    int tid = threadIdx.x, lid = tid & 31;
    int g = lid >> 2, tg = lid & 3;
    int wid = tid >> 5, wm = wid & 3, wn = wid >> 2;
    int rowBase = blockIdx.x * 128;

    float acc[2][4][4];
#pragma unroll
    for (int mt = 0; mt < 2; mt++)
#pragma unroll
        for (int nt = 0; nt < 4; nt++)
#pragma unroll
            for (int e = 0; e < 4; e++) acc[mt][nt][e] = 0.f;

    // prologue: prefetch tap 0 into stage 0
    g2_fill_async(sb, sb + A_BYTES, neigh, rowBase, n, 0, tid);
    asm volatile("cp.async.commit_group;" ::: "memory");

    for (int k = 0; k < 27; k++) {
        int cur = k & 1;
        if (k + 1 < 27) {
            int nxt = 1 - cur;
            g2_fill_async(sb + (uint32_t)nxt * STAGE_B,
                          sb + (uint32_t)nxt * STAGE_B + A_BYTES,
                          neigh, rowBase, n, k + 1, tid);
            asm volatile("cp.async.commit_group;" ::: "memory");
            asm volatile("cp.async.wait_group 1;" ::: "memory");
        } else {
            asm volatile("cp.async.wait_group 0;" ::: "memory");
        }
        __syncthreads();
        tile_mma_h(sb + (uint32_t)cur * STAGE_B,
                   sb + (uint32_t)cur * STAGE_B + A_BYTES, wm, wn, lid, acc);
        __syncthreads();
    }
    tile_epilogue((float*)smem, g_y2, 64, rowBase, n, wm, wn, g, tg, tid, 256, acc);
}

// ---------------- stage 3: y3 = h2h @ W3 -> fp16 y3  (grid.y = col slab) ----
__global__ __launch_bounds__(256) void gemm3_tc_kernel(int n) {
    extern __shared__ char smem[];
    uint32_t sA = (uint32_t)__cvta_generic_to_shared(smem);
    uint32_t sB = sA + A_BYTES;
    __half* As = (__half*)smem;
    __half* Bs = (__half*)(smem + A_BYTES);
    int tid = threadIdx.x, lid = tid & 31;
    int g = lid >> 2, tg = lid & 3;
    int wid = tid >> 5, wm = wid & 3, wn = wid >> 2;
    int rowBase = blockIdx.x * 128;
    int colBase = blockIdx.y * 64;

    float acc[2][4][4];
#pragma unroll
    for (int mt = 0; mt < 2; mt++)
#pragma unroll
        for (int nt = 0; nt < 4; nt++)
#pragma unroll
            for (int e = 0; e < 4; e++) acc[mt][nt][e] = 0.f;

#pragma unroll
    for (int i = 0; i < 4; i++) {
        int fid = tid + 256 * i;
        int r = fid >> 3, j = fid & 7;
        int gr = rowBase + r;
        uint4 v = make_uint4(0u, 0u, 0u, 0u);
        if (gr < n) v = *(const uint4*)&g_h2h[(size_t)gr * 64 + j * 8];
        *(uint4*)((char*)As + r * 144 + j * 16) = v;
    }
#pragma unroll
    for (int i = 0; i < 2; i++) {
        int fid = tid + 256 * i;
        int r = fid >> 3, j = fid & 7;
        *(uint4*)((char*)Bs + r * 144 + j * 16) =
            *(const uint4*)&g_W3h[(size_t)(colBase + r) * 64 + j * 8];
    }
    __syncthreads();
    tile_mma_h(sA, sB, wm, wn, lid, acc);
    __syncthreads();
    tile_epilogue_h((float*)smem, g_y3h + colBase, 256, rowBase, n, wm, wn, g, tg, tid,
                    512 + colBase, acc);
}

// out = relu(bn3(y3) + x)   (BN3 scale/shift recomputed per block; y3 fp16)
__global__ __launch_bounds__(256) void final_kernel(const float* __restrict__ x,
                                                    const float* __restrict__ gamma,
                                                    const float* __restrict__ beta,
                                                    float* __restrict__ out,
                                                    int n, float invN) {
    __shared__ float s_sc[256], s_sh[256];
    int tid = threadIdx.x;
    {
        float mean = g_sum[512 + tid] * invN;
        float var  = g_sumsq[512 + tid] * invN - mean * mean;
        float s = gamma[tid] * rsqrtf(var + EPS_BN);
        s_sc[tid] = s;
        s_sh[tid] = beta[tid] - mean * s;
    }
    __syncthreads();
    long i = (long)blockIdx.x * 256 + tid;
    long total4 = (long)n * 64;
    if (i < total4) {
        int c4 = (int)(i & 63) * 4;
        uint2 yh = *(const uint2*)&g_y3h[i * 4];
        float2 y01 = __half22float2(*(__half2*)&yh.x);
        float2 y23 = __half22float2(*(__half2*)&yh.y);
        float4 xi = *(const float4*)&x[i * 4];
        float4 s = *(const float4*)&s_sc[c4];
        float4 t = *(const float4*)&s_sh[c4];
        float4 o;
        o.x = fmaxf(fmaf(y01.x, s.x, t.x) + xi.x, 0.f);
        o.y = fmaxf(fmaf(y01.y, s.y, t.y) + xi.y, 0.f);
        o.z = fmaxf(fmaf(y23.x, s.z, t.z) + xi.z, 0.f);
        o.w = fmaxf(fmaf(y23.y, s.w, t.w) + xi.w, 0.f);
        *(float4*)&out[i * 4] = o;
    }
}

// ---------------------------------------------------------------------------
extern "C" void kernel_launch(void* const* d_in, const int* in_sizes, int n_in,
                              void* d_out, int out_size) {
    const float* x     = (const float*)d_in[0];
    const int*   neigh = (const int*)d_in[1];
    const float* W1 = (const float*)d_in[3];
    const float* g1 = (const float*)d_in[4];
    const float* b1 = (const float*)d_in[5];
    const float* W2 = (const float*)d_in[6];
    const float* g2 = (const float*)d_in[7];
    const float* b2 = (const float*)d_in[8];
    const float* W3 = (const float*)d_in[9];
    const float* g3 = (const float*)d_in[10];
    const float* b3 = (const float*)d_in[11];
    float* out = (float*)d_out;

    int n = in_sizes[0] / 256;
    int NB = (n + 127) / 128;
    float invN = 1.0f / (float)n;

    static bool attr_done = false;
    if (!attr_done) {
        cudaFuncSetAttribute(gemm1_tc_kernel, cudaFuncAttributeMaxDynamicSharedMemorySize, SM1);
        cudaFuncSetAttribute(gemm2_tc_kernel, cudaFuncAttributeMaxDynamicSharedMemorySize, SM2);
        cudaFuncSetAttribute(gemm3_tc_kernel, cudaFuncAttributeMaxDynamicSharedMemorySize, SM1);
        attr_done = true;
    }

    int NH = (int)(((long)n * 16 + 255) / 256);

    prep_kernel<<<(110592 + 255) / 256, 256>>>(W1, W2, W3);
    gemm1_tc_kernel<<<NB, 256, SM1>>>(x, n);
    prep_h_kernel<<<NH, 256>>>(g1, b1, 0, n, invN);
    gemm2_tc_kernel<<<NB, 256, SM2>>>(neigh, n);
    prep_h_kernel<<<NH, 256>>>(g2, b2, 1, n, invN);
    gemm3_tc_kernel<<<dim3(NB, 4), 256, SM1>>>(n);
    final_kernel<<<(int)(((long)n * 64 + 255) / 256), 256>>>(x, g3, b3, out, n, invN);
}